// round 1
// baseline (speedup 1.0000x reference)
#include <cuda_runtime.h>
#include <cuda_bf16.h>
#include <math.h>

// ---------------- problem constants ----------------
#define B   16
#define S   256
#define NV  196
#define D   768
#define FF  2048
#define VOC 30522
#define NL  6
#define NH  8
#define HD  96          // D / NH
#define MX  (B*S)       // 4096 rows of x
#define MKV (B*NV)      // 3136 rows of fv
#define MDEC (B*(S-1))  // 4080 rows of dec

// ---------------- scratch (device globals; no allocation) ----------------
__device__ float g_x   [MX * D];        // running activation
__device__ float g_qkv [MX * 3*D];      // qkv projections / reused as FF hidden
__device__ float g_attn[MX * D];        // attention output (pre out-proj)
__device__ float g_y   [MX * D];        // sublayer output (pre-residual)
__device__ float g_q   [MX * D];        // cross-attn Q
__device__ float g_kv  [MKV * 2*D];     // cross-attn K,V
__device__ float g_dec [MDEC * D];      // dec = x[:, :S-1, :]

// ---------------- add positional encoding ----------------
__global__ void add_pe_kernel(float* __restrict__ x, const float* __restrict__ te) {
    int row = blockIdx.x;            // b*S + s
    int s   = row % S;
    int tid = threadIdx.x;           // 256 threads, 3 elems each
    size_t base = (size_t)row * D;
    #pragma unroll
    for (int i = 0; i < 3; i++) {
        int d = tid + i * 256;
        int i2 = d & ~1;
        float div = expf(-(float)i2 * (9.210340371976184f / (float)D));
        float ang = (float)s * div;
        float pe  = (d & 1) ? cosf(ang) : sinf(ang);
        x[base + d] = te[base + d] + pe;
    }
}

// ---------------- tiled SGEMM: C[m][n] = sum_k A[m][k]*W[n][k] + bias[n] ----------------
// A: MxK row-major, W: NxK row-major (PyTorch/JAX linear layout), optional relu.
#define BM 64
#define BN 64
#define BK 16
__global__ __launch_bounds__(256) void sgemm_bias_kernel(
    const float* __restrict__ A, const float* __restrict__ W,
    const float* __restrict__ bias, float* __restrict__ C,
    int M, int N, int K, int relu)
{
    __shared__ float As[BK][BM];
    __shared__ float Bs[BK][BN];
    int tid = threadIdx.x;
    int tx = tid & 15, ty = tid >> 4;          // 16x16 thread grid
    int row0 = blockIdx.y * BM;
    int col0 = blockIdx.x * BN;
    int lk = tid & 15;                          // k within tile for loads
    int lr = tid >> 4;                          // row/col base for loads

    float acc[4][4] = {};
    for (int k0 = 0; k0 < K; k0 += BK) {
        #pragma unroll
        for (int p = 0; p < 4; p++) {
            int r  = lr + p * 16;
            int gr = row0 + r, gk = k0 + lk;
            As[lk][r] = (gr < M && gk < K) ? A[(size_t)gr * K + gk] : 0.f;
            int gn = col0 + r;
            Bs[lk][r] = (gn < N && gk < K) ? W[(size_t)gn * K + gk] : 0.f;
        }
        __syncthreads();
        #pragma unroll
        for (int k = 0; k < BK; k++) {
            float a[4], b[4];
            #pragma unroll
            for (int i = 0; i < 4; i++) a[i] = As[k][ty * 4 + i];
            #pragma unroll
            for (int j = 0; j < 4; j++) b[j] = Bs[k][tx * 4 + j];
            #pragma unroll
            for (int i = 0; i < 4; i++)
                #pragma unroll
                for (int j = 0; j < 4; j++)
                    acc[i][j] = fmaf(a[i], b[j], acc[i][j]);
        }
        __syncthreads();
    }
    #pragma unroll
    for (int i = 0; i < 4; i++) {
        int gr = row0 + ty * 4 + i;
        if (gr >= M) continue;
        #pragma unroll
        for (int j = 0; j < 4; j++) {
            int gn = col0 + tx * 4 + j;
            if (gn >= N) continue;
            float v = acc[i][j] + (bias ? bias[gn] : 0.f);
            if (relu) v = fmaxf(v, 0.f);
            C[(size_t)gr * N + gn] = v;
        }
    }
}

static inline void launch_gemm(const float* A, const float* W, const float* bias,
                               float* C, int M, int N, int K, int relu) {
    dim3 grid((N + BN - 1) / BN, (M + BM - 1) / BM);
    sgemm_bias_kernel<<<grid, 256>>>(A, W, bias, C, M, N, K, relu);
}

// ---------------- attention: one block per (b*NH+h, qi) ----------------
// Q rows: stride q_stride, head offset q_off + h*HD
// KV rows: stride kv_stride, K at k_off + h*HD, V at v_off + h*HD
__global__ __launch_bounds__(128) void attention_kernel(
    const float* __restrict__ Q, int q_stride, int q_off,
    const float* __restrict__ KV, int kv_stride, int k_off, int v_off,
    float* __restrict__ O, int o_stride,
    int Lq, int Lk, int causal, float scale)
{
    __shared__ float qs[HD];
    __shared__ float ps[S];       // Lk <= 256
    __shared__ float red[8];
    int qi  = blockIdx.x;
    int bh  = blockIdx.y;
    int b   = bh / NH, h = bh % NH;
    int tid = threadIdx.x;        // 128 = 4 warps

    const float* qrow = Q + (size_t)(b * Lq + qi) * q_stride + q_off + h * HD;
    if (tid < HD) qs[tid] = qrow[tid];
    __syncthreads();

    const float* kbase = KV + (size_t)b * Lk * kv_stride + k_off + h * HD;
    float lmax = -1e30f;
    for (int ki = tid; ki < Lk; ki += 128) {
        float sc;
        if (causal && ki > qi) {
            sc = -1e9f;
        } else {
            const float* krow = kbase + (size_t)ki * kv_stride;
            float acc = 0.f;
            #pragma unroll
            for (int d = 0; d < HD; d++) acc = fmaf(qs[d], krow[d], acc);
            sc = acc * scale;
        }
        ps[ki] = sc;
        lmax = fmaxf(lmax, sc);
    }
    // block max
    #pragma unroll
    for (int off = 16; off; off >>= 1) lmax = fmaxf(lmax, __shfl_xor_sync(~0u, lmax, off));
    if ((tid & 31) == 0) red[tid >> 5] = lmax;
    __syncthreads();
    float gmax = fmaxf(fmaxf(red[0], red[1]), fmaxf(red[2], red[3]));
    __syncthreads();

    float lsum = 0.f;
    for (int ki = tid; ki < Lk; ki += 128) {
        float e = __expf(ps[ki] - gmax);
        ps[ki] = e;
        lsum += e;
    }
    #pragma unroll
    for (int off = 16; off; off >>= 1) lsum += __shfl_xor_sync(~0u, lsum, off);
    if ((tid & 31) == 0) red[tid >> 5] = lsum;
    __syncthreads();                 // also makes all ps[] writes visible
    float inv = 1.f / (red[0] + red[1] + red[2] + red[3]);

    const float* vbase = KV + (size_t)b * Lk * kv_stride + v_off + h * HD;
    if (tid < HD) {
        float acc = 0.f;
        for (int ki = 0; ki < Lk; ki++)
            acc = fmaf(ps[ki], vbase[(size_t)ki * kv_stride + tid], acc);
        O[(size_t)(b * Lq + qi) * o_stride + h * HD + tid] = acc * inv;
    }
}

// ---------------- fused residual + layernorm: X = LN(X + Y) * w + b ----------------
__global__ __launch_bounds__(256) void residual_ln_kernel(
    float* __restrict__ X, const float* __restrict__ Y,
    const float* __restrict__ w, const float* __restrict__ b)
{
    __shared__ float red[8];
    int row = blockIdx.x;
    int tid = threadIdx.x;
    size_t base = (size_t)row * D;
    float v0 = X[base + tid]       + Y[base + tid];
    float v1 = X[base + tid + 256] + Y[base + tid + 256];
    float v2 = X[base + tid + 512] + Y[base + tid + 512];
    float s = v0 + v1 + v2;
    #pragma unroll
    for (int off = 16; off; off >>= 1) s += __shfl_xor_sync(~0u, s, off);
    if ((tid & 31) == 0) red[tid >> 5] = s;
    __syncthreads();
    float tot = 0.f;
    #pragma unroll
    for (int i = 0; i < 8; i++) tot += red[i];
    float mean = tot * (1.f / (float)D);
    float d0 = v0 - mean, d1 = v1 - mean, d2 = v2 - mean;
    float q = d0 * d0 + d1 * d1 + d2 * d2;
    #pragma unroll
    for (int off = 16; off; off >>= 1) q += __shfl_xor_sync(~0u, q, off);
    __syncthreads();                       // protect red[] reuse
    if ((tid & 31) == 0) red[tid >> 5] = q;
    __syncthreads();
    float vq = 0.f;
    #pragma unroll
    for (int i = 0; i < 8; i++) vq += red[i];
    float var = vq * (1.f / (float)D);
    float rs = rsqrtf(var + 1e-5f);
    X[base + tid]       = d0 * rs * w[tid]       + b[tid];
    X[base + tid + 256] = d1 * rs * w[tid + 256] + b[tid + 256];
    X[base + tid + 512] = d2 * rs * w[tid + 512] + b[tid + 512];
}

// ---------------- dec copy: drop last seq position per batch ----------------
__global__ void copy_dec_kernel(float* __restrict__ dec, const float* __restrict__ x) {
    int r   = blockIdx.x;            // 0..MDEC-1
    int b   = r / (S - 1);
    int s   = r % (S - 1);
    int tid = threadIdx.x;
    size_t src = (size_t)(b * S + s) * D;
    size_t dst = (size_t)r * D;
    #pragma unroll
    for (int i = 0; i < 3; i++) dec[dst + tid + i * 256] = x[src + tid + i * 256];
}

// ---------------- row softmax over D for F_t ----------------
__global__ __launch_bounds__(256) void softmax_rows_kernel(
    const float* __restrict__ X, float* __restrict__ O)
{
    __shared__ float red[8];
    int row = blockIdx.x;
    int tid = threadIdx.x;
    size_t base = (size_t)row * D;
    float v0 = X[base + tid], v1 = X[base + tid + 256], v2 = X[base + tid + 512];
    float m = fmaxf(fmaxf(v0, v1), v2);
    #pragma unroll
    for (int off = 16; off; off >>= 1) m = fmaxf(m, __shfl_xor_sync(~0u, m, off));
    if ((tid & 31) == 0) red[tid >> 5] = m;
    __syncthreads();
    float gm = red[0];
    #pragma unroll
    for (int i = 1; i < 8; i++) gm = fmaxf(gm, red[i]);
    float e0 = expf(v0 - gm), e1 = expf(v1 - gm), e2 = expf(v2 - gm);
    float s = e0 + e1 + e2;
    #pragma unroll
    for (int off = 16; off; off >>= 1) s += __shfl_xor_sync(~0u, s, off);
    __syncthreads();
    if ((tid & 31) == 0) red[tid >> 5] = s;
    __syncthreads();
    float tot = 0.f;
    #pragma unroll
    for (int i = 0; i < 8; i++) tot += red[i];
    float inv = 1.f / tot;
    O[base + tid]       = e0 * inv;
    O[base + tid + 256] = e1 * inv;
    O[base + tid + 512] = e2 * inv;
}

// ---------------- orchestration ----------------
extern "C" void kernel_launch(void* const* d_in, const int* in_sizes, int n_in,
                              void* d_out, int out_size)
{
    const float* fv          = (const float*)d_in[0];
    const float* target_embed= (const float*)d_in[1];
    const float* self_in_w   = (const float*)d_in[2];
    const float* self_in_b   = (const float*)d_in[3];
    const float* self_out_w  = (const float*)d_in[4];
    const float* self_out_b  = (const float*)d_in[5];
    const float* cross_in_w  = (const float*)d_in[6];
    const float* cross_in_b  = (const float*)d_in[7];
    const float* cross_out_w = (const float*)d_in[8];
    const float* cross_out_b = (const float*)d_in[9];
    const float* lin1_w      = (const float*)d_in[10];
    const float* lin1_b      = (const float*)d_in[11];
    const float* lin2_w      = (const float*)d_in[12];
    const float* lin2_b      = (const float*)d_in[13];
    const float* ln_w        = (const float*)d_in[14];
    const float* ln_b        = (const float*)d_in[15];
    const float* fc_out_w    = (const float*)d_in[16];
    float* out = (float*)d_out;

    float *px, *pqkv, *pattn, *py, *pq, *pkv, *pdec;
    cudaGetSymbolAddress((void**)&px,   g_x);
    cudaGetSymbolAddress((void**)&pqkv, g_qkv);
    cudaGetSymbolAddress((void**)&pattn,g_attn);
    cudaGetSymbolAddress((void**)&py,   g_y);
    cudaGetSymbolAddress((void**)&pq,   g_q);
    cudaGetSymbolAddress((void**)&pkv,  g_kv);
    cudaGetSymbolAddress((void**)&pdec, g_dec);

    const float scale = rsqrtf((float)HD);

    // x = target_embed + PE
    add_pe_kernel<<<MX, 256>>>(px, target_embed);

    for (int l = 0; l < NL; l++) {
        const float* siw = self_in_w   + (size_t)l * 3*D * D;
        const float* sib = self_in_b   + (size_t)l * 3*D;
        const float* sow = self_out_w  + (size_t)l * D * D;
        const float* sob = self_out_b  + (size_t)l * D;
        const float* ciw = cross_in_w  + (size_t)l * 3*D * D;
        const float* cib = cross_in_b  + (size_t)l * 3*D;
        const float* cow = cross_out_w + (size_t)l * D * D;
        const float* cob = cross_out_b + (size_t)l * D;
        const float* l1w = lin1_w      + (size_t)l * FF * D;
        const float* l1b = lin1_b      + (size_t)l * FF;
        const float* l2w = lin2_w      + (size_t)l * D * FF;
        const float* l2b = lin2_b      + (size_t)l * D;
        const float* lnw = ln_w        + (size_t)l * 3 * D;
        const float* lnb = ln_b        + (size_t)l * 3 * D;

        // ---- self attention ----
        launch_gemm(px, siw, sib, pqkv, MX, 3*D, D, 0);
        attention_kernel<<<dim3(S, B*NH), 128>>>(
            pqkv, 3*D, 0, pqkv, 3*D, D, 2*D, pattn, D, S, S, 1, scale);
        launch_gemm(pattn, sow, sob, py, MX, D, D, 0);
        residual_ln_kernel<<<MX, 256>>>(px, py, lnw + 0*D, lnb + 0*D);

        // ---- cross attention ----
        launch_gemm(px, ciw, cib, pq, MX, D, D, 0);                       // Q (first D rows of W)
        launch_gemm(fv, ciw + (size_t)D*D, cib + D, pkv, MKV, 2*D, D, 0); // K,V from memory
        attention_kernel<<<dim3(S, B*NH), 128>>>(
            pq, D, 0, pkv, 2*D, 0, D, pattn, D, S, NV, 0, scale);
        launch_gemm(pattn, cow, cob, py, MX, D, D, 0);
        residual_ln_kernel<<<MX, 256>>>(px, py, lnw + 1*D, lnb + 1*D);

        // ---- feed forward (hidden reuses g_qkv) ----
        launch_gemm(px, l1w, l1b, pqkv, MX, FF, D, 1);
        launch_gemm(pqkv, l2w, l2b, py, MX, D, FF, 0);
        residual_ln_kernel<<<MX, 256>>>(px, py, lnw + 2*D, lnb + 2*D);
    }

    // ---- final heads ----
    copy_dec_kernel<<<MDEC, 256>>>(pdec, px);
    // logits = dec @ fc_out_w.T  -> out[0 : MDEC*VOC)
    launch_gemm(pdec, fc_out_w, nullptr, out, MDEC, VOC, D, 0);
    // F_t = softmax(dec, axis=-1) -> out[MDEC*VOC : )
    softmax_rows_kernel<<<MDEC, 256>>>(pdec, out + (size_t)MDEC * VOC);
}

// round 4
// speedup vs baseline: 2.7494x; 2.7494x over previous
#include <cuda_runtime.h>
#include <cuda_bf16.h>
#include <math.h>

// ---------------- problem constants ----------------
#define B   16
#define S   256
#define NV  196
#define D   768
#define FF  2048
#define VOC 30522
#define NL  6
#define NH  8
#define HD  96          // D / NH
#define MX  (B*S)       // 4096 rows of x
#define MKV (B*NV)      // 3136 rows of fv
#define MDEC (B*(S-1))  // 4080 rows of dec

// ---------------- scratch (device globals; no allocation) ----------------
__device__ float g_x   [MX * D];
__device__ float g_qkv [MX * 3*D];
__device__ float g_attn[MX * D];
__device__ float g_y   [MX * D];
__device__ float g_q   [MX * D];
__device__ float g_kv  [MKV * 2*D];
__device__ float g_dec [MDEC * D];

// ---------------- add positional encoding ----------------
__global__ void add_pe_kernel(float* __restrict__ x, const float* __restrict__ te) {
    int row = blockIdx.x;
    int s   = row % S;
    int tid = threadIdx.x;
    size_t base = (size_t)row * D;
    #pragma unroll
    for (int i = 0; i < 3; i++) {
        int d = tid + i * 256;
        int i2 = d & ~1;
        float div = expf(-(float)i2 * (9.210340371976184f / (float)D));
        float ang = (float)s * div;
        float pe  = (d & 1) ? cosf(ang) : sinf(ang);
        x[base + d] = te[base + d] + pe;
    }
}

// ---------------- SGEMM 128x128, 8x8 per thread, reg-prefetch ----------------
// C[m][n] = sum_k A[m][k]*W[n][k] + bias[n] ; optional relu. K must be mult of 16.
#define BM 128
#define BN 128
#define BK 16
__global__ __launch_bounds__(256, 2) void sgemm_bias_kernel(
    const float* __restrict__ A, const float* __restrict__ W,
    const float* __restrict__ bias, float* __restrict__ C,
    int M, int N, int K, int relu)
{
    __shared__ float As[BK][BM];
    __shared__ float Bs[BK][BN];
    int tid = threadIdx.x;
    int tx = tid & 15, ty = tid >> 4;          // 16x16 thread grid, 8x8 each
    int row0 = blockIdx.y * BM;
    int col0 = blockIdx.x * BN;

    // loader mapping: 512 float4 per tile per operand; 2 per thread
    int lrow[2], lkv[2];
    #pragma unroll
    for (int i = 0; i < 2; i++) { int idx = i * 256 + tid; lrow[i] = idx >> 2; lkv[i] = idx & 3; }

    float4 ra[2], rb[2];
    // prefetch first tile
    #pragma unroll
    for (int i = 0; i < 2; i++) {
        int gr = row0 + lrow[i];
        int gk = lkv[i] * 4;
        if (gr < M) ra[i] = *(const float4*)&A[(size_t)gr * K + gk];
        else        ra[i] = make_float4(0.f, 0.f, 0.f, 0.f);
        int gn = col0 + lrow[i];
        if (gn < N) rb[i] = *(const float4*)&W[(size_t)gn * K + gk];
        else        rb[i] = make_float4(0.f, 0.f, 0.f, 0.f);
    }

    float acc[8][8] = {};
    for (int k0 = 0; k0 < K; k0 += BK) {
        #pragma unroll
        for (int i = 0; i < 2; i++) {
            int r = lrow[i], kb = lkv[i] * 4;
            As[kb + 0][r] = ra[i].x; As[kb + 1][r] = ra[i].y;
            As[kb + 2][r] = ra[i].z; As[kb + 3][r] = ra[i].w;
            Bs[kb + 0][r] = rb[i].x; Bs[kb + 1][r] = rb[i].y;
            Bs[kb + 2][r] = rb[i].z; Bs[kb + 3][r] = rb[i].w;
        }
        __syncthreads();
        if (k0 + BK < K) {
            #pragma unroll
            for (int i = 0; i < 2; i++) {
                int gr = row0 + lrow[i];
                int gk = k0 + BK + lkv[i] * 4;
                if (gr < M) ra[i] = *(const float4*)&A[(size_t)gr * K + gk];
                else        ra[i] = make_float4(0.f, 0.f, 0.f, 0.f);
                int gn = col0 + lrow[i];
                if (gn < N) rb[i] = *(const float4*)&W[(size_t)gn * K + gk];
                else        rb[i] = make_float4(0.f, 0.f, 0.f, 0.f);
            }
        }
        #pragma unroll
        for (int k = 0; k < BK; k++) {
            float a[8], b[8];
            *(float4*)&a[0] = *(const float4*)&As[k][ty * 8];
            *(float4*)&a[4] = *(const float4*)&As[k][ty * 8 + 4];
            *(float4*)&b[0] = *(const float4*)&Bs[k][tx * 8];
            *(float4*)&b[4] = *(const float4*)&Bs[k][tx * 8 + 4];
            #pragma unroll
            for (int i = 0; i < 8; i++)
                #pragma unroll
                for (int j = 0; j < 8; j++)
                    acc[i][j] = fmaf(a[i], b[j], acc[i][j]);
        }
        __syncthreads();
    }
    #pragma unroll
    for (int i = 0; i < 8; i++) {
        int gr = row0 + ty * 8 + i;
        if (gr >= M) continue;
        #pragma unroll
        for (int j = 0; j < 8; j++) {
            int gn = col0 + tx * 8 + j;
            if (gn >= N) continue;
            float v = acc[i][j] + (bias ? bias[gn] : 0.f);
            if (relu) v = fmaxf(v, 0.f);
            C[(size_t)gr * N + gn] = v;
        }
    }
}

static inline void launch_gemm(const float* A, const float* W, const float* bias,
                               float* C, int M, int N, int K, int relu) {
    dim3 grid((N + BN - 1) / BN, (M + BM - 1) / BM);
    sgemm_bias_kernel<<<grid, 256>>>(A, W, bias, C, M, N, K, relu);
}

// ---------------- flash attention: 32-q x 32-k tiles, online softmax ----------------
#define QT 32
#define KT 32
__global__ __launch_bounds__(256) void flash_attn_kernel(
    const float* __restrict__ Q, int q_stride,
    const float* __restrict__ KV, int kv_stride, int k_off, int v_off,
    float* __restrict__ O,
    int Lq, int Lk, int causal, float scale)
{
    __shared__ float Qs[QT][HD + 1];
    __shared__ float Ks[KT][HD + 1];
    __shared__ float Vs[KT][HD + 1];
    int bh = blockIdx.y;
    int b = bh >> 3, h = bh & 7;
    int q0 = blockIdx.x * QT;
    int tid = threadIdx.x;
    int qr = tid >> 3;         // 0..31 query row in tile
    int sub = tid & 7;         // 8 threads per row
    int qi = q0 + qr;

    const float* qbase = Q + (size_t)(b * Lq + q0) * q_stride + h * HD;
    for (int i = tid; i < QT * HD; i += 256) {
        int r = i / HD, d = i % HD;
        Qs[r][d] = qbase[(size_t)r * q_stride + d];
    }
    __syncthreads();

    const float* kbase = KV + (size_t)b * Lk * kv_stride + k_off + h * HD;
    const float* vbase = KV + (size_t)b * Lk * kv_stride + v_off + h * HD;

    float m = -1e30f, lsum = 0.f;
    float o[12];
    #pragma unroll
    for (int j = 0; j < 12; j++) o[j] = 0.f;

    int kend = causal ? (q0 + QT < Lk ? q0 + QT : Lk) : Lk;
    int lanebase = (tid & 31) & ~7;

    for (int k0 = 0; k0 < kend; k0 += KT) {
        for (int i = tid; i < KT * HD; i += 256) {
            int r = i / HD, d = i % HD;
            int ki = k0 + r;
            if (ki < Lk) {
                Ks[r][d] = kbase[(size_t)ki * kv_stride + d];
                Vs[r][d] = vbase[(size_t)ki * kv_stride + d];
            } else {
                Ks[r][d] = 0.f;
                Vs[r][d] = 0.f;
            }
        }
        __syncthreads();

        float sc[4];
        #pragma unroll
        for (int c = 0; c < 4; c++) {
            int kk = sub * 4 + c;
            int ki = k0 + kk;
            float acc = 0.f;
            #pragma unroll
            for (int d = 0; d < HD; d += 4) {
                acc = fmaf(Qs[qr][d + 0], Ks[kk][d + 0], acc);
                acc = fmaf(Qs[qr][d + 1], Ks[kk][d + 1], acc);
                acc = fmaf(Qs[qr][d + 2], Ks[kk][d + 2], acc);
                acc = fmaf(Qs[qr][d + 3], Ks[kk][d + 3], acc);
            }
            acc *= scale;
            if (ki >= Lk || (causal && ki > qi)) acc = -1e30f;
            sc[c] = acc;
        }
        float tm = fmaxf(fmaxf(sc[0], sc[1]), fmaxf(sc[2], sc[3]));
        #pragma unroll
        for (int off = 4; off; off >>= 1) tm = fmaxf(tm, __shfl_xor_sync(~0u, tm, off));
        float mnew = fmaxf(m, tm);
        float corr = __expf(m - mnew);
        float p[4];
        float psum = 0.f;
        #pragma unroll
        for (int c = 0; c < 4; c++) { p[c] = __expf(sc[c] - mnew); psum += p[c]; }
        #pragma unroll
        for (int off = 4; off; off >>= 1) psum += __shfl_xor_sync(~0u, psum, off);
        lsum = lsum * corr + psum;
        #pragma unroll
        for (int j = 0; j < 12; j++) o[j] *= corr;
        m = mnew;
        #pragma unroll
        for (int kk = 0; kk < KT; kk++) {
            float pv = __shfl_sync(~0u, p[kk & 3], lanebase + (kk >> 2));
            #pragma unroll
            for (int j = 0; j < 12; j++)
                o[j] = fmaf(pv, Vs[kk][sub * 12 + j], o[j]);
        }
        __syncthreads();
    }

    float inv = 1.f / lsum;
    float* orow = O + (size_t)(b * Lq + qi) * D + h * HD + sub * 12;
    #pragma unroll
    for (int j = 0; j < 12; j++) orow[j] = o[j] * inv;
}

// ---------------- fused residual + layernorm ----------------
__global__ __launch_bounds__(256) void residual_ln_kernel(
    float* __restrict__ X, const float* __restrict__ Y,
    const float* __restrict__ w, const float* __restrict__ b)
{
    __shared__ float red[8];
    int row = blockIdx.x;
    int tid = threadIdx.x;
    size_t base = (size_t)row * D;
    float v0 = X[base + tid]       + Y[base + tid];
    float v1 = X[base + tid + 256] + Y[base + tid + 256];
    float v2 = X[base + tid + 512] + Y[base + tid + 512];
    float s = v0 + v1 + v2;
    #pragma unroll
    for (int off = 16; off; off >>= 1) s += __shfl_xor_sync(~0u, s, off);
    if ((tid & 31) == 0) red[tid >> 5] = s;
    __syncthreads();
    float tot = 0.f;
    #pragma unroll
    for (int i = 0; i < 8; i++) tot += red[i];
    float mean = tot * (1.f / (float)D);
    float d0 = v0 - mean, d1 = v1 - mean, d2 = v2 - mean;
    float q = d0 * d0 + d1 * d1 + d2 * d2;
    #pragma unroll
    for (int off = 16; off; off >>= 1) q += __shfl_xor_sync(~0u, q, off);
    __syncthreads();
    if ((tid & 31) == 0) red[tid >> 5] = q;
    __syncthreads();
    float vq = 0.f;
    #pragma unroll
    for (int i = 0; i < 8; i++) vq += red[i];
    float var = vq * (1.f / (float)D);
    float rs = rsqrtf(var + 1e-5f);
    X[base + tid]       = d0 * rs * w[tid]       + b[tid];
    X[base + tid + 256] = d1 * rs * w[tid + 256] + b[tid + 256];
    X[base + tid + 512] = d2 * rs * w[tid + 512] + b[tid + 512];
}

// ---------------- dec copy ----------------
__global__ void copy_dec_kernel(float* __restrict__ dec, const float* __restrict__ x) {
    int r   = blockIdx.x;
    int b   = r / (S - 1);
    int s   = r % (S - 1);
    int tid = threadIdx.x;
    size_t src = (size_t)(b * S + s) * D;
    size_t dst = (size_t)r * D;
    #pragma unroll
    for (int i = 0; i < 3; i++) dec[dst + tid + i * 256] = x[src + tid + i * 256];
}

// ---------------- row softmax over D for F_t ----------------
__global__ __launch_bounds__(256) void softmax_rows_kernel(
    const float* __restrict__ X, float* __restrict__ O)
{
    __shared__ float red[8];
    int row = blockIdx.x;
    int tid = threadIdx.x;
    size_t base = (size_t)row * D;
    float v0 = X[base + tid], v1 = X[base + tid + 256], v2 = X[base + tid + 512];
    float m = fmaxf(fmaxf(v0, v1), v2);
    #pragma unroll
    for (int off = 16; off; off >>= 1) m = fmaxf(m, __shfl_xor_sync(~0u, m, off));
    if ((tid & 31) == 0) red[tid >> 5] = m;
    __syncthreads();
    float gm = red[0];
    #pragma unroll
    for (int i = 1; i < 8; i++) gm = fmaxf(gm, red[i]);
    float e0 = expf(v0 - gm), e1 = expf(v1 - gm), e2 = expf(v2 - gm);
    float s = e0 + e1 + e2;
    #pragma unroll
    for (int off = 16; off; off >>= 1) s += __shfl_xor_sync(~0u, s, off);
    __syncthreads();
    if ((tid & 31) == 0) red[tid >> 5] = s;
    __syncthreads();
    float tot = 0.f;
    #pragma unroll
    for (int i = 0; i < 8; i++) tot += red[i];
    float inv = 1.f / tot;
    O[base + tid]       = e0 * inv;
    O[base + tid + 256] = e1 * inv;
    O[base + tid + 512] = e2 * inv;
}

// ---------------- orchestration ----------------
extern "C" void kernel_launch(void* const* d_in, const int* in_sizes, int n_in,
                              void* d_out, int out_size)
{
    const float* fv          = (const float*)d_in[0];
    const float* target_embed= (const float*)d_in[1];
    const float* self_in_w   = (const float*)d_in[2];
    const float* self_in_b   = (const float*)d_in[3];
    const float* self_out_w  = (const float*)d_in[4];
    const float* self_out_b  = (const float*)d_in[5];
    const float* cross_in_w  = (const float*)d_in[6];
    const float* cross_in_b  = (const float*)d_in[7];
    const float* cross_out_w = (const float*)d_in[8];
    const float* cross_out_b = (const float*)d_in[9];
    const float* lin1_w      = (const float*)d_in[10];
    const float* lin1_b      = (const float*)d_in[11];
    const float* lin2_w      = (const float*)d_in[12];
    const float* lin2_b      = (const float*)d_in[13];
    const float* ln_w        = (const float*)d_in[14];
    const float* ln_b        = (const float*)d_in[15];
    const float* fc_out_w    = (const float*)d_in[16];
    float* out = (float*)d_out;

    float *px, *pqkv, *pattn, *py, *pq, *pkv, *pdec;
    cudaGetSymbolAddress((void**)&px,   g_x);
    cudaGetSymbolAddress((void**)&pqkv, g_qkv);
    cudaGetSymbolAddress((void**)&pattn,g_attn);
    cudaGetSymbolAddress((void**)&py,   g_y);
    cudaGetSymbolAddress((void**)&pq,   g_q);
    cudaGetSymbolAddress((void**)&pkv,  g_kv);
    cudaGetSymbolAddress((void**)&pdec, g_dec);

    const float scale = rsqrtf((float)HD);

    add_pe_kernel<<<MX, 256>>>(px, target_embed);

    for (int l = 0; l < NL; l++) {
        const float* siw = self_in_w   + (size_t)l * 3*D * D;
        const float* sib = self_in_b   + (size_t)l * 3*D;
        const float* sow = self_out_w  + (size_t)l * D * D;
        const float* sob = self_out_b  + (size_t)l * D;
        const float* ciw = cross_in_w  + (size_t)l * 3*D * D;
        const float* cib = cross_in_b  + (size_t)l * 3*D;
        const float* cow = cross_out_w + (size_t)l * D * D;
        const float* cob = cross_out_b + (size_t)l * D;
        const float* l1w = lin1_w      + (size_t)l * FF * D;
        const float* l1b = lin1_b      + (size_t)l * FF;
        const float* l2w = lin2_w      + (size_t)l * D * FF;
        const float* l2b = lin2_b      + (size_t)l * D;
        const float* lnw = ln_w        + (size_t)l * 3 * D;
        const float* lnb = ln_b        + (size_t)l * 3 * D;

        // ---- self attention ----
        launch_gemm(px, siw, sib, pqkv, MX, 3*D, D, 0);
        flash_attn_kernel<<<dim3(S / QT, B * NH), 256>>>(
            pqkv, 3*D, pqkv, 3*D, D, 2*D, pattn, S, S, 1, scale);
        launch_gemm(pattn, sow, sob, py, MX, D, D, 0);
        residual_ln_kernel<<<MX, 256>>>(px, py, lnw + 0*D, lnb + 0*D);

        // ---- cross attention ----
        launch_gemm(px, ciw, cib, pq, MX, D, D, 0);
        launch_gemm(fv, ciw + (size_t)D*D, cib + D, pkv, MKV, 2*D, D, 0);
        flash_attn_kernel<<<dim3(S / QT, B * NH), 256>>>(
            pq, D, pkv, 2*D, 0, D, pattn, S, NV, 0, scale);
        launch_gemm(pattn, cow, cob, py, MX, D, D, 0);
        residual_ln_kernel<<<MX, 256>>>(px, py, lnw + 1*D, lnb + 1*D);

        // ---- feed forward ----
        launch_gemm(px, l1w, l1b, pqkv, MX, FF, D, 1);
        launch_gemm(pqkv, l2w, l2b, py, MX, D, FF, 0);
        residual_ln_kernel<<<MX, 256>>>(px, py, lnw + 2*D, lnb + 2*D);
    }

    // ---- final heads ----
    copy_dec_kernel<<<MDEC, 256>>>(pdec, px);
    launch_gemm(pdec, fc_out_w, nullptr, out, MDEC, VOC, D, 0);
    softmax_rows_kernel<<<MDEC, 256>>>(pdec, out + (size_t)MDEC * VOC);
}

// round 7
// speedup vs baseline: 6.8774x; 2.5014x over previous
#include <cuda_runtime.h>
#include <cuda_bf16.h>
#include <math.h>
#include <stdint.h>

// ---------------- problem constants ----------------
#define B   16
#define S   256
#define NV  196
#define D   768
#define FF  2048
#define VOC 30522
#define NL  6
#define NH  8
#define HD  96          // D / NH
#define MX  (B*S)       // 4096 rows of x
#define MKV (B*NV)      // 3136 rows of fv
#define MDEC (B*(S-1))  // 4080 rows of dec

// ---------------- scratch (device globals; no allocation) ----------------
__device__ float g_x   [MX * D];
__device__ float g_qkv [MX * 3*D];
__device__ float g_attn[MX * D];
__device__ float g_y   [MX * D];
__device__ float g_q   [MX * D];
__device__ float g_kv  [MKV * 2*D];
__device__ float g_dec [MDEC * D];

// ---------------- helpers ----------------
__device__ __forceinline__ float to_tf32(float x) {
    uint32_t u;
    asm("cvt.rna.tf32.f32 %0, %1;" : "=r"(u) : "f"(x));
    return __uint_as_float(u);
}

__device__ __forceinline__ void mma_tf32(float c[4],
    uint32_t a0, uint32_t a1, uint32_t a2, uint32_t a3,
    uint32_t b0, uint32_t b1)
{
    asm volatile(
        "mma.sync.aligned.m16n8k8.row.col.f32.tf32.tf32.f32 "
        "{%0,%1,%2,%3},{%4,%5,%6,%7},{%8,%9},{%0,%1,%2,%3};\n"
        : "+f"(c[0]), "+f"(c[1]), "+f"(c[2]), "+f"(c[3])
        : "r"(a0), "r"(a1), "r"(a2), "r"(a3), "r"(b0), "r"(b1));
}

// ---------------- add positional encoding ----------------
__global__ void add_pe_kernel(float* __restrict__ x, const float* __restrict__ te) {
    int row = blockIdx.x;
    int s   = row % S;
    int tid = threadIdx.x;
    size_t base = (size_t)row * D;
    #pragma unroll
    for (int i = 0; i < 3; i++) {
        int d = tid + i * 256;
        int i2 = d & ~1;
        float div = expf(-(float)i2 * (9.210340371976184f / (float)D));
        float ang = (float)s * div;
        float pe  = (d & 1) ? cosf(ang) : sinf(ang);
        x[base + d] = te[base + d] + pe;
    }
}

// ---------------- TF32 tensor-core GEMM ----------------
// C[m][n] = sum_k A[m][k]*W[n][k] + bias[n] ; optional relu.
// Block tile 128x128, BK=32, 8 warps (2x4), warp tile 64x32.
// K must be a multiple of 32 (768, 2048 both are).
#define BM 128
#define BN 128
#define BK 32
#define LDK (BK + 4)     // 36 floats per row -> conflict-free fragment loads
__global__ __launch_bounds__(256) void tf32_gemm_kernel(
    const float* __restrict__ A, const float* __restrict__ W,
    const float* __restrict__ bias, float* __restrict__ C,
    int M, int N, int K, int relu)
{
    __shared__ float As[BM * LDK];
    __shared__ float Bs[BN * LDK];

    int tid  = threadIdx.x;
    int lane = tid & 31;
    int wid  = tid >> 5;
    int gid  = lane >> 2;     // group id 0..7
    int tig  = lane & 3;      // thread in group 0..3
    int wm   = wid >> 2;      // 0..1  -> m offset wm*64
    int wn   = wid & 3;       // 0..3  -> n offset wn*32

    int row0 = blockIdx.y * BM;
    int col0 = blockIdx.x * BN;

    // loader mapping: 128 rows x 8 float4 (BK=32) = 1024 float4 per operand; 4 per thread
    int lrow[4], lkv[4];
    #pragma unroll
    for (int i = 0; i < 4; i++) { int idx = i * 256 + tid; lrow[i] = idx >> 3; lkv[i] = idx & 7; }

    float4 ra[4], rb[4];
    // prefetch first k-tile
    #pragma unroll
    for (int i = 0; i < 4; i++) {
        int gr = row0 + lrow[i];
        int gk = lkv[i] * 4;
        if (gr < M) ra[i] = *(const float4*)&A[(size_t)gr * K + gk];
        else        ra[i] = make_float4(0.f, 0.f, 0.f, 0.f);
        int gn = col0 + lrow[i];
        if (gn < N) rb[i] = *(const float4*)&W[(size_t)gn * K + gk];
        else        rb[i] = make_float4(0.f, 0.f, 0.f, 0.f);
    }

    float acc[4][4][4] = {};   // [mtile][ntile][reg]

    for (int k0 = 0; k0 < K; k0 += BK) {
        // store prefetched tile to smem (tf32-rounded)
        #pragma unroll
        for (int i = 0; i < 4; i++) {
            float4 a4 = ra[i], b4 = rb[i];
            a4.x = to_tf32(a4.x); a4.y = to_tf32(a4.y); a4.z = to_tf32(a4.z); a4.w = to_tf32(a4.w);
            b4.x = to_tf32(b4.x); b4.y = to_tf32(b4.y); b4.z = to_tf32(b4.z); b4.w = to_tf32(b4.w);
            *(float4*)&As[lrow[i] * LDK + lkv[i] * 4] = a4;
            *(float4*)&Bs[lrow[i] * LDK + lkv[i] * 4] = b4;
        }
        __syncthreads();
        // prefetch next k-tile
        if (k0 + BK < K) {
            #pragma unroll
            for (int i = 0; i < 4; i++) {
                int gr = row0 + lrow[i];
                int gk = k0 + BK + lkv[i] * 4;
                if (gr < M) ra[i] = *(const float4*)&A[(size_t)gr * K + gk];
                else        ra[i] = make_float4(0.f, 0.f, 0.f, 0.f);
                int gn = col0 + lrow[i];
                if (gn < N) rb[i] = *(const float4*)&W[(size_t)gn * K + gk];
                else        rb[i] = make_float4(0.f, 0.f, 0.f, 0.f);
            }
        }
        // compute: 4 mma-k steps of 8
        #pragma unroll
        for (int kk = 0; kk < BK; kk += 8) {
            uint32_t af[4][4];
            #pragma unroll
            for (int mt = 0; mt < 4; mt++) {
                int rbase = wm * 64 + mt * 16;
                af[mt][0] = __float_as_uint(As[(rbase + gid)     * LDK + kk + tig]);
                af[mt][1] = __float_as_uint(As[(rbase + gid + 8) * LDK + kk + tig]);
                af[mt][2] = __float_as_uint(As[(rbase + gid)     * LDK + kk + tig + 4]);
                af[mt][3] = __float_as_uint(As[(rbase + gid + 8) * LDK + kk + tig + 4]);
            }
            uint32_t bf[4][2];
            #pragma unroll
            for (int nt = 0; nt < 4; nt++) {
                int cbase = wn * 32 + nt * 8;
                bf[nt][0] = __float_as_uint(Bs[(cbase + gid) * LDK + kk + tig]);
                bf[nt][1] = __float_as_uint(Bs[(cbase + gid) * LDK + kk + tig + 4]);
            }
            #pragma unroll
            for (int mt = 0; mt < 4; mt++)
                #pragma unroll
                for (int nt = 0; nt < 4; nt++)
                    mma_tf32(acc[mt][nt], af[mt][0], af[mt][1], af[mt][2], af[mt][3],
                             bf[nt][0], bf[nt][1]);
        }
        __syncthreads();
    }

    // epilogue: c0:(gid, 2tig) c1:(gid, 2tig+1) c2:(gid+8, 2tig) c3:(gid+8, 2tig+1)
    #pragma unroll
    for (int mt = 0; mt < 4; mt++) {
        int r_lo = row0 + wm * 64 + mt * 16 + gid;
        int r_hi = r_lo + 8;
        #pragma unroll
        for (int nt = 0; nt < 4; nt++) {
            int gn = col0 + wn * 32 + nt * 8 + 2 * tig;
            if (gn >= N) continue;
            float b0 = bias ? bias[gn]     : 0.f;
            float b1 = bias ? bias[gn + 1] : 0.f;
            if (r_lo < M) {
                float v0 = acc[mt][nt][0] + b0;
                float v1 = acc[mt][nt][1] + b1;
                if (relu) { v0 = fmaxf(v0, 0.f); v1 = fmaxf(v1, 0.f); }
                *(float2*)&C[(size_t)r_lo * N + gn] = make_float2(v0, v1);
            }
            if (r_hi < M) {
                float v2 = acc[mt][nt][2] + b0;
                float v3 = acc[mt][nt][3] + b1;
                if (relu) { v2 = fmaxf(v2, 0.f); v3 = fmaxf(v3, 0.f); }
                *(float2*)&C[(size_t)r_hi * N + gn] = make_float2(v2, v3);
            }
        }
    }
}

static inline void launch_gemm(const float* A, const float* W, const float* bias,
                               float* C, int M, int N, int K, int relu) {
    dim3 grid((N + BN - 1) / BN, (M + BM - 1) / BM);
    tf32_gemm_kernel<<<grid, 256>>>(A, W, bias, C, M, N, K, relu);
}

// ---------------- flash attention: 32-q x 32-k tiles, online softmax ----------------
#define QT 32
#define KT 32
__global__ __launch_bounds__(256) void flash_attn_kernel(
    const float* __restrict__ Q, int q_stride,
    const float* __restrict__ KV, int kv_stride, int k_off, int v_off,
    float* __restrict__ O,
    int Lq, int Lk, int causal, float scale)
{
    __shared__ float Qs[QT][HD + 1];
    __shared__ float Ks[KT][HD + 1];
    __shared__ float Vs[KT][HD + 1];
    int bh = blockIdx.y;
    int b = bh >> 3, h = bh & 7;
    int q0 = blockIdx.x * QT;
    int tid = threadIdx.x;
    int qr = tid >> 3;         // 0..31 query row in tile
    int sub = tid & 7;         // 8 threads per row
    int qi = q0 + qr;

    const float* qbase = Q + (size_t)(b * Lq + q0) * q_stride + h * HD;
    for (int i = tid; i < QT * HD; i += 256) {
        int r = i / HD, d = i % HD;
        Qs[r][d] = qbase[(size_t)r * q_stride + d];
    }
    __syncthreads();

    const float* kbase = KV + (size_t)b * Lk * kv_stride + k_off + h * HD;
    const float* vbase = KV + (size_t)b * Lk * kv_stride + v_off + h * HD;

    float m = -1e30f, lsum = 0.f;
    float o[12];
    #pragma unroll
    for (int j = 0; j < 12; j++) o[j] = 0.f;

    int kend = causal ? (q0 + QT < Lk ? q0 + QT : Lk) : Lk;
    int lanebase = (tid & 31) & ~7;

    for (int k0 = 0; k0 < kend; k0 += KT) {
        for (int i = tid; i < KT * HD; i += 256) {
            int r = i / HD, d = i % HD;
            int ki = k0 + r;
            if (ki < Lk) {
                Ks[r][d] = kbase[(size_t)ki * kv_stride + d];
                Vs[r][d] = vbase[(size_t)ki * kv_stride + d];
            } else {
                Ks[r][d] = 0.f;
                Vs[r][d] = 0.f;
            }
        }
        __syncthreads();

        float sc[4];
        #pragma unroll
        for (int c = 0; c < 4; c++) {
            int kk = sub * 4 + c;
            int ki = k0 + kk;
            float acc = 0.f;
            #pragma unroll
            for (int d = 0; d < HD; d += 4) {
                acc = fmaf(Qs[qr][d + 0], Ks[kk][d + 0], acc);
                acc = fmaf(Qs[qr][d + 1], Ks[kk][d + 1], acc);
                acc = fmaf(Qs[qr][d + 2], Ks[kk][d + 2], acc);
                acc = fmaf(Qs[qr][d + 3], Ks[kk][d + 3], acc);
            }
            acc *= scale;
            if (ki >= Lk || (causal && ki > qi)) acc = -1e30f;
            sc[c] = acc;
        }
        float tm = fmaxf(fmaxf(sc[0], sc[1]), fmaxf(sc[2], sc[3]));
        #pragma unroll
        for (int off = 4; off; off >>= 1) tm = fmaxf(tm, __shfl_xor_sync(~0u, tm, off));
        float mnew = fmaxf(m, tm);
        float corr = __expf(m - mnew);
        float p[4];
        float psum = 0.f;
        #pragma unroll
        for (int c = 0; c < 4; c++) { p[c] = __expf(sc[c] - mnew); psum += p[c]; }
        #pragma unroll
        for (int off = 4; off; off >>= 1) psum += __shfl_xor_sync(~0u, psum, off);
        lsum = lsum * corr + psum;
        #pragma unroll
        for (int j = 0; j < 12; j++) o[j] *= corr;
        m = mnew;
        #pragma unroll
        for (int kk = 0; kk < KT; kk++) {
            float pv = __shfl_sync(~0u, p[kk & 3], lanebase + (kk >> 2));
            #pragma unroll
            for (int j = 0; j < 12; j++)
                o[j] = fmaf(pv, Vs[kk][sub * 12 + j], o[j]);
        }
        __syncthreads();
    }

    float inv = 1.f / lsum;
    float* orow = O + (size_t)(b * Lq + qi) * D + h * HD + sub * 12;
    #pragma unroll
    for (int j = 0; j < 12; j++) orow[j] = o[j] * inv;
}

// ---------------- fused residual + layernorm ----------------
__global__ __launch_bounds__(256) void residual_ln_kernel(
    float* __restrict__ X, const float* __restrict__ Y,
    const float* __restrict__ w, const float* __restrict__ b)
{
    __shared__ float red[8];
    int row = blockIdx.x;
    int tid = threadIdx.x;
    size_t base = (size_t)row * D;
    float v0 = X[base + tid]       + Y[base + tid];
    float v1 = X[base + tid + 256] + Y[base + tid + 256];
    float v2 = X[base + tid + 512] + Y[base + tid + 512];
    float s = v0 + v1 + v2;
    #pragma unroll
    for (int off = 16; off; off >>= 1) s += __shfl_xor_sync(~0u, s, off);
    if ((tid & 31) == 0) red[tid >> 5] = s;
    __syncthreads();
    float tot = 0.f;
    #pragma unroll
    for (int i = 0; i < 8; i++) tot += red[i];
    float mean = tot * (1.f / (float)D);
    float d0 = v0 - mean, d1 = v1 - mean, d2 = v2 - mean;
    float q = d0 * d0 + d1 * d1 + d2 * d2;
    #pragma unroll
    for (int off = 16; off; off >>= 1) q += __shfl_xor_sync(~0u, q, off);
    __syncthreads();
    if ((tid & 31) == 0) red[tid >> 5] = q;
    __syncthreads();
    float vq = 0.f;
    #pragma unroll
    for (int i = 0; i < 8; i++) vq += red[i];
    float var = vq * (1.f / (float)D);
    float rs = rsqrtf(var + 1e-5f);
    X[base + tid]       = d0 * rs * w[tid]       + b[tid];
    X[base + tid + 256] = d1 * rs * w[tid + 256] + b[tid + 256];
    X[base + tid + 512] = d2 * rs * w[tid + 512] + b[tid + 512];
}

// ---------------- dec copy ----------------
__global__ void copy_dec_kernel(float* __restrict__ dec, const float* __restrict__ x) {
    int r   = blockIdx.x;
    int b   = r / (S - 1);
    int s   = r % (S - 1);
    int tid = threadIdx.x;
    size_t src = (size_t)(b * S + s) * D;
    size_t dst = (size_t)r * D;
    #pragma unroll
    for (int i = 0; i < 3; i++) dec[dst + tid + i * 256] = x[src + tid + i * 256];
}

// ---------------- row softmax over D for F_t ----------------
__global__ __launch_bounds__(256) void softmax_rows_kernel(
    const float* __restrict__ X, float* __restrict__ O)
{
    __shared__ float red[8];
    int row = blockIdx.x;
    int tid = threadIdx.x;
    size_t base = (size_t)row * D;
    float v0 = X[base + tid], v1 = X[base + tid + 256], v2 = X[base + tid + 512];
    float m = fmaxf(fmaxf(v0, v1), v2);
    #pragma unroll
    for (int off = 16; off; off >>= 1) m = fmaxf(m, __shfl_xor_sync(~0u, m, off));
    if ((tid & 31) == 0) red[tid >> 5] = m;
    __syncthreads();
    float gm = red[0];
    #pragma unroll
    for (int i = 1; i < 8; i++) gm = fmaxf(gm, red[i]);
    float e0 = expf(v0 - gm), e1 = expf(v1 - gm), e2 = expf(v2 - gm);
    float s = e0 + e1 + e2;
    #pragma unroll
    for (int off = 16; off; off >>= 1) s += __shfl_xor_sync(~0u, s, off);
    __syncthreads();
    if ((tid & 31) == 0) red[tid >> 5] = s;
    __syncthreads();
    float tot = 0.f;
    #pragma unroll
    for (int i = 0; i < 8; i++) tot += red[i];
    float inv = 1.f / tot;
    O[base + tid]       = e0 * inv;
    O[base + tid + 256] = e1 * inv;
    O[base + tid + 512] = e2 * inv;
}

// ---------------- orchestration ----------------
extern "C" void kernel_launch(void* const* d_in, const int* in_sizes, int n_in,
                              void* d_out, int out_size)
{
    const float* fv          = (const float*)d_in[0];
    const float* target_embed= (const float*)d_in[1];
    const float* self_in_w   = (const float*)d_in[2];
    const float* self_in_b   = (const float*)d_in[3];
    const float* self_out_w  = (const float*)d_in[4];
    const float* self_out_b  = (const float*)d_in[5];
    const float* cross_in_w  = (const float*)d_in[6];
    const float* cross_in_b  = (const float*)d_in[7];
    const float* cross_out_w = (const float*)d_in[8];
    const float* cross_out_b = (const float*)d_in[9];
    const float* lin1_w      = (const float*)d_in[10];
    const float* lin1_b      = (const float*)d_in[11];
    const float* lin2_w      = (const float*)d_in[12];
    const float* lin2_b      = (const float*)d_in[13];
    const float* ln_w        = (const float*)d_in[14];
    const float* ln_b        = (const float*)d_in[15];
    const float* fc_out_w    = (const float*)d_in[16];
    float* out = (float*)d_out;

    float *px, *pqkv, *pattn, *py, *pq, *pkv, *pdec;
    cudaGetSymbolAddress((void**)&px,   g_x);
    cudaGetSymbolAddress((void**)&pqkv, g_qkv);
    cudaGetSymbolAddress((void**)&pattn,g_attn);
    cudaGetSymbolAddress((void**)&py,   g_y);
    cudaGetSymbolAddress((void**)&pq,   g_q);
    cudaGetSymbolAddress((void**)&pkv,  g_kv);
    cudaGetSymbolAddress((void**)&pdec, g_dec);

    const float scale = rsqrtf((float)HD);

    add_pe_kernel<<<MX, 256>>>(px, target_embed);

    for (int l = 0; l < NL; l++) {
        const float* siw = self_in_w   + (size_t)l * 3*D * D;
        const float* sib = self_in_b   + (size_t)l * 3*D;
        const float* sow = self_out_w  + (size_t)l * D * D;
        const float* sob = self_out_b  + (size_t)l * D;
        const float* ciw = cross_in_w  + (size_t)l * 3*D * D;
        const float* cib = cross_in_b  + (size_t)l * 3*D;
        const float* cow = cross_out_w + (size_t)l * D * D;
        const float* cob = cross_out_b + (size_t)l * D;
        const float* l1w = lin1_w      + (size_t)l * FF * D;
        const float* l1b = lin1_b      + (size_t)l * FF;
        const float* l2w = lin2_w      + (size_t)l * D * FF;
        const float* l2b = lin2_b      + (size_t)l * D;
        const float* lnw = ln_w        + (size_t)l * 3 * D;
        const float* lnb = ln_b        + (size_t)l * 3 * D;

        // ---- self attention ----
        launch_gemm(px, siw, sib, pqkv, MX, 3*D, D, 0);
        flash_attn_kernel<<<dim3(S / QT, B * NH), 256>>>(
            pqkv, 3*D, pqkv, 3*D, D, 2*D, pattn, S, S, 1, scale);
        launch_gemm(pattn, sow, sob, py, MX, D, D, 0);
        residual_ln_kernel<<<MX, 256>>>(px, py, lnw + 0*D, lnb + 0*D);

        // ---- cross attention ----
        launch_gemm(px, ciw, cib, pq, MX, D, D, 0);
        launch_gemm(fv, ciw + (size_t)D*D, cib + D, pkv, MKV, 2*D, D, 0);
        flash_attn_kernel<<<dim3(S / QT, B * NH), 256>>>(
            pq, D, pkv, 2*D, 0, D, pattn, S, NV, 0, scale);
        launch_gemm(pattn, cow, cob, py, MX, D, D, 0);
        residual_ln_kernel<<<MX, 256>>>(px, py, lnw + 1*D, lnb + 1*D);

        // ---- feed forward ----
        launch_gemm(px, l1w, l1b, pqkv, MX, FF, D, 1);
        launch_gemm(pqkv, l2w, l2b, py, MX, D, FF, 0);
        residual_ln_kernel<<<MX, 256>>>(px, py, lnw + 2*D, lnb + 2*D);
    }

    // ---- final heads ----
    copy_dec_kernel<<<MDEC, 256>>>(pdec, px);
    launch_gemm(pdec, fc_out_w, nullptr, out, MDEC, VOC, D, 0);
    softmax_rows_kernel<<<MDEC, 256>>>(pdec, out + (size_t)MDEC * VOC);
}